// round 1
// baseline (speedup 1.0000x reference)
#include <cuda_runtime.h>
#include <math.h>

#define N 4096
#define D 256
#define KK 3
#define MAXC 1024

// ---------------- device scratch (static: no allocations allowed) ----------
__device__ float g_wx[KK * N * D];   // 12 MiB: wx[k][n][d]
__device__ float g_al[KK * N * 4];   // al[k][n][r]
__device__ float g_ar[KK * N * 4];   // ar[k][n][r]

// ---------------- kernel 1: wx[k] = x @ W_t[k] (fp32, 64x64x16 tiles) ------
__global__ __launch_bounds__(256) void k_gemm(const float* __restrict__ X,
                                              const float* __restrict__ Wt) {
    const int kb = blockIdx.z;
    const float* B = Wt + (size_t)kb * D * D;
    float* C = g_wx + (size_t)kb * N * D;
    const int row0 = blockIdx.x * 64;
    const int col0 = blockIdx.y * 64;

    __shared__ float As[16][64];   // [kdim][row]
    __shared__ float Bs[16][64];   // [kdim][col]

    const int tid = threadIdx.x;
    const int ty = tid >> 4;       // 0..15 -> rows ty*4..ty*4+3
    const int tx = tid & 15;       // 0..15 -> cols tx*4..tx*4+3

    float acc[4][4];
#pragma unroll
    for (int i = 0; i < 4; i++)
#pragma unroll
        for (int j = 0; j < 4; j++) acc[i][j] = 0.f;

    for (int k0 = 0; k0 < D; k0 += 16) {
        {   // load A tile: 64 rows x 16 k
            int r = tid >> 2;
            int kc = (tid & 3) * 4;
            float4 v = *(const float4*)(X + (size_t)(row0 + r) * D + k0 + kc);
            As[kc + 0][r] = v.x; As[kc + 1][r] = v.y;
            As[kc + 2][r] = v.z; As[kc + 3][r] = v.w;
        }
        {   // load B tile: 16 k x 64 cols
            int kr = tid >> 4;
            int c = (tid & 15) * 4;
            float4 v = *(const float4*)(B + (size_t)(k0 + kr) * D + col0 + c);
            Bs[kr][c + 0] = v.x; Bs[kr][c + 1] = v.y;
            Bs[kr][c + 2] = v.z; Bs[kr][c + 3] = v.w;
        }
        __syncthreads();
#pragma unroll
        for (int p = 0; p < 16; p++) {
            float a[4], b[4];
#pragma unroll
            for (int i = 0; i < 4; i++) a[i] = As[p][ty * 4 + i];
#pragma unroll
            for (int j = 0; j < 4; j++) b[j] = Bs[p][tx * 4 + j];
#pragma unroll
            for (int i = 0; i < 4; i++)
#pragma unroll
                for (int j = 0; j < 4; j++) acc[i][j] = fmaf(a[i], b[j], acc[i][j]);
        }
        __syncthreads();
    }
#pragma unroll
    for (int i = 0; i < 4; i++)
#pragma unroll
        for (int j = 0; j < 4; j++)
            C[(size_t)(row0 + ty * 4 + i) * D + col0 + tx * 4 + j] = acc[i][j];
}

// ---------------- kernel 2: al/ar = wx @ W_{l,r}[k].T (warp per row) ------
__global__ __launch_bounds__(256) void k_alar(const float* __restrict__ Wl,
                                              const float* __restrict__ Wr) {
    const int idx = blockIdx.x * 8 + (threadIdx.x >> 5);  // 0 .. KK*N-1
    const int lane = threadIdx.x & 31;
    const int k = idx >> 12;          // N = 4096 = 2^12
    const int n = idx & (N - 1);

    const float* wxr = g_wx + (size_t)(k * N + n) * D;
    const float* wl = Wl + (size_t)k * 4 * D;
    const float* wr = Wr + (size_t)k * 4 * D;

    float s[8] = {0, 0, 0, 0, 0, 0, 0, 0};
#pragma unroll 2
    for (int c = lane; c < D; c += 32) {
        float v = wxr[c];
        s[0] = fmaf(v, wl[0 * D + c], s[0]);
        s[1] = fmaf(v, wl[1 * D + c], s[1]);
        s[2] = fmaf(v, wl[2 * D + c], s[2]);
        s[3] = fmaf(v, wl[3 * D + c], s[3]);
        s[4] = fmaf(v, wr[0 * D + c], s[4]);
        s[5] = fmaf(v, wr[1 * D + c], s[5]);
        s[6] = fmaf(v, wr[2 * D + c], s[6]);
        s[7] = fmaf(v, wr[3 * D + c], s[7]);
    }
#pragma unroll
    for (int r = 0; r < 8; r++)
#pragma unroll
        for (int o = 16; o; o >>= 1) s[r] += __shfl_xor_sync(0xffffffffu, s[r], o);

    if (lane == 0) {
        float* a = g_al + (size_t)(k * N + n) * 4;
        float* b = g_ar + (size_t)(k * N + n) * 4;
        a[0] = s[0]; a[1] = s[1]; a[2] = s[2]; a[3] = s[3];
        b[0] = s[4]; b[1] = s[5]; b[2] = s[6]; b[3] = s[7];
    }
}

// ---------------- kernel 3: per-row sparse attention + softmax + ELU -------
__global__ __launch_bounds__(256) void k_main(const int* __restrict__ sup,
                                              const int* __restrict__ asup,
                                              float* __restrict__ out) {
    const int n = blockIdx.x;
    const int tid = threadIdx.x;
    const int lane = tid & 31;
    const int warp = tid >> 5;

    __shared__ int   s_packed[MAXC];     // col | (flags<<16)
    __shared__ float s_sc[KK][MAXC];     // scores, then probs (unnormalized)
    __shared__ float s_al[12];           // al[k][r] for this row
    __shared__ float s_wred[8];
    __shared__ int   s_iwred[8];
    __shared__ float s_b;
    __shared__ int   s_total;

    if (tid < 12) s_al[tid] = g_al[(size_t)((tid >> 2) * N + n) * 4 + (tid & 3)];

    // ---- phase A: scan all 6 mask rows once, deterministic compaction ----
    const int4* p0 = (const int4*)(asup + (size_t)0 * N * N + (size_t)n * N);
    const int4* p1 = (const int4*)(asup + (size_t)1 * N * N + (size_t)n * N);
    const int4* p2 = (const int4*)(asup + (size_t)2 * N * N + (size_t)n * N);
    const int4* q0 = (const int4*)(sup  + (size_t)0 * N * N + (size_t)n * N);
    const int4* q1 = (const int4*)(sup  + (size_t)1 * N * N + (size_t)n * N);
    const int4* q2 = (const int4*)(sup  + (size_t)2 * N * N + (size_t)n * N);

    int flags[16];
    int cnt = 0;
#pragma unroll
    for (int j = 0; j < 4; j++) {
        int idx = tid * 4 + j;
        int4 a0 = __ldg(&p0[idx]); int4 a1 = __ldg(&p1[idx]); int4 a2 = __ldg(&p2[idx]);
        int4 b0 = __ldg(&q0[idx]); int4 b1 = __ldg(&q1[idx]); int4 b2 = __ldg(&q2[idx]);
        int f;
        f = (a0.x != 0) | ((a1.x != 0) << 1) | ((a2.x != 0) << 2)
          | ((b0.x != 0) << 3) | ((b1.x != 0) << 4) | ((b2.x != 0) << 5);
        flags[j * 4 + 0] = f; cnt += (f != 0);
        f = (a0.y != 0) | ((a1.y != 0) << 1) | ((a2.y != 0) << 2)
          | ((b0.y != 0) << 3) | ((b1.y != 0) << 4) | ((b2.y != 0) << 5);
        flags[j * 4 + 1] = f; cnt += (f != 0);
        f = (a0.z != 0) | ((a1.z != 0) << 1) | ((a2.z != 0) << 2)
          | ((b0.z != 0) << 3) | ((b1.z != 0) << 4) | ((b2.z != 0) << 5);
        flags[j * 4 + 2] = f; cnt += (f != 0);
        f = (a0.w != 0) | ((a1.w != 0) << 1) | ((a2.w != 0) << 2)
          | ((b0.w != 0) << 3) | ((b1.w != 0) << 4) | ((b2.w != 0) << 5);
        flags[j * 4 + 3] = f; cnt += (f != 0);
    }

    // exclusive prefix over per-thread counts (order-preserving => deterministic)
    int inc = cnt;
#pragma unroll
    for (int o = 1; o < 32; o <<= 1) {
        int t = __shfl_up_sync(0xffffffffu, inc, o);
        if (lane >= o) inc += t;
    }
    if (lane == 31) s_iwred[warp] = inc;
    __syncthreads();
    if (tid < 8) {
        int v = s_iwred[tid];
#pragma unroll
        for (int o = 1; o < 8; o <<= 1) {
            int t = __shfl_up_sync(0xffu, v, o);
            if (tid >= o) v += t;
        }
        s_iwred[tid] = v;
        if (tid == 7) s_total = v;
    }
    __syncthreads();
    int off = (warp ? s_iwred[warp - 1] : 0) + inc - cnt;
#pragma unroll
    for (int c = 0; c < 16; c++) {
        int f = flags[c];
        if (f) {
            if (off < MAXC) s_packed[off] = (tid * 16 + c) | (f << 16);
            off++;
        }
    }
    __syncthreads();
    const int cnt_all = min(s_total, MAXC);

    // ---- phase B: scores for all 3 k ----
    for (int i = tid; i < cnt_all; i += 256) {
        int pk = s_packed[i];
        int m = pk & 0xFFFF;
        int f = pk >> 16;
#pragma unroll
        for (int k = 0; k < KK; k++) {
            float4 arv = *(const float4*)(g_ar + (size_t)(k * N + m) * 4);
            float sc = 0.f;
            if (f & 1) sc += s_al[k * 4 + 0] + arv.x;
            if (f & 2) sc += s_al[k * 4 + 1] + arv.y;
            if (f & 4) sc += s_al[k * 4 + 2] + arv.z;
            if (f & (8 << k)) sc += s_al[k * 4 + 3] + arv.w;
            bool act = (f & (7 | (8 << k))) != 0;
            s_sc[k][i] = (act && sc != 0.f) ? sc : -INFINITY;
        }
    }
    __syncthreads();

    // ---- phase C: per-k softmax + gather-accumulate ----
    float acc = 0.f;  // this thread owns output element d = tid
#pragma unroll 1
    for (int k = 0; k < KK; k++) {
        float mx = -INFINITY;
        for (int i = tid; i < cnt_all; i += 256) mx = fmaxf(mx, s_sc[k][i]);
#pragma unroll
        for (int o = 16; o; o >>= 1) mx = fmaxf(mx, __shfl_xor_sync(0xffffffffu, mx, o));
        if (lane == 0) s_wred[warp] = mx;
        __syncthreads();
        if (tid < 8) {
            float v = s_wred[tid];
#pragma unroll
            for (int o = 4; o; o >>= 1) v = fmaxf(v, __shfl_xor_sync(0xffu, v, o));
            if (tid == 0) s_b = v;
        }
        __syncthreads();
        mx = s_b;
        __syncthreads();

        if (mx != -INFINITY) {     // uniform branch
            float sum = 0.f;
            for (int i = tid; i < cnt_all; i += 256) {
                float s = s_sc[k][i];
                float e = (s == -INFINITY) ? 0.f : expf(s - mx);
                s_sc[k][i] = e;
                sum += e;
            }
#pragma unroll
            for (int o = 16; o; o >>= 1) sum += __shfl_xor_sync(0xffffffffu, sum, o);
            if (lane == 0) s_wred[warp] = sum;
            __syncthreads();
            if (tid < 8) {
                float v = s_wred[tid];
#pragma unroll
                for (int o = 4; o; o >>= 1) v += __shfl_xor_sync(0xffu, v, o);
                if (tid == 0) s_b = v;
            }
            __syncthreads();
            const float inv = 1.f / s_b;
            const float* wxk = g_wx + (size_t)k * N * D;
#pragma unroll 2
            for (int i = 0; i < cnt_all; i++) {
                float p = s_sc[k][i];
                if (p > 0.f) {     // uniform across block (smem value)
                    int m = s_packed[i] & 0xFFFF;
                    acc = fmaf(p * inv, __ldg(wxk + (size_t)m * D + tid), acc);
                }
            }
        }
        __syncthreads();
    }

    float r = acc > 0.f ? acc : expm1f(acc);
    out[(size_t)n * D + tid] = r;
}

// ---------------- launcher -------------------------------------------------
extern "C" void kernel_launch(void* const* d_in, const int* in_sizes, int n_in,
                              void* d_out, int out_size) {
    const float* x    = (const float*)d_in[0];
    const int*   sup  = (const int*)d_in[1];   // supports [K,N,N]
    const int*   asup = (const int*)d_in[2];   // atten_supports [R,N,N]
    const float* Wt   = (const float*)d_in[3]; // [K,DIN,DOUT]
    const float* Wl   = (const float*)d_in[4]; // [K,R+1,DOUT]
    const float* Wr   = (const float*)d_in[5]; // [K,R+1,DOUT]
    float* out = (float*)d_out;

    dim3 g1(N / 64, D / 64, KK);
    k_gemm<<<g1, 256>>>(x, Wt);
    k_alar<<<(KK * N) / 8, 256>>>(Wl, Wr);
    k_main<<<N, 256>>>(sup, asup, out);
    (void)in_sizes; (void)n_in; (void)out_size;
}

// round 14
// speedup vs baseline: 1.8003x; 1.8003x over previous
#include <cuda_runtime.h>
#include <math.h>

#define N 4096
#define D 256
#define KK 3
#define MAXC 1024

typedef unsigned long long ull;

// ---------------- device scratch (static: no allocations allowed) ----------
__device__ float g_wx[KK * N * D];     // 12 MiB: wx[k][n][d]
__device__ float g_al[KK * N * 4];     // al[k][n][r]
__device__ float g_ar[KK * N * 4];     // ar[k][n][r]
__device__ int   g_packed[N * MAXC];   // 16 MiB: per-row compacted col|flags
__device__ int   g_cnt[N];             // per-row active-column count

// ---------------- packed f32x2 helpers -------------------------------------
__device__ __forceinline__ ull pk2(float x, float y) {
    ull r; asm("mov.b64 %0, {%1, %2};" : "=l"(r) : "f"(x), "f"(y)); return r;
}
__device__ __forceinline__ float2 upk2(ull v) {
    float2 r; asm("mov.b64 {%0, %1}, %2;" : "=f"(r.x), "=f"(r.y) : "l"(v)); return r;
}
__device__ __forceinline__ void fma2(ull& d, ull a, ull b) {
    asm("fma.rn.f32x2 %0, %1, %2, %3;" : "=l"(d) : "l"(a), "l"(b), "l"(d));
}

// ---------------- kernel 1: wx[k] = x @ W_t[k] (128x64 tiles, f32x2) -------
__global__ __launch_bounds__(256) void k_gemm(const float* __restrict__ X,
                                              const float* __restrict__ Wt) {
    const int kb = blockIdx.z;
    const float* B = Wt + (size_t)kb * D * D;
    float* C = g_wx + (size_t)kb * N * D;
    const int row0 = blockIdx.x * 128;
    const int col0 = blockIdx.y * 64;

    __shared__ float As[16][128];   // [kdim][row]
    __shared__ float Bs[16][64];    // [kdim][col]

    const int tid = threadIdx.x;
    const int ty8 = (tid >> 4) * 8;    // 8 rows per thread
    const int tx4 = (tid & 15) * 4;    // 4 cols per thread

    ull acc[4][4];                      // [rowpair][col], each holds 2 rows
#pragma unroll
    for (int i = 0; i < 4; i++)
#pragma unroll
        for (int j = 0; j < 4; j++) acc[i][j] = pk2(0.f, 0.f);

    for (int k0 = 0; k0 < D; k0 += 16) {
#pragma unroll
        for (int s = tid; s < 512; s += 256) {
            int r = s >> 2;
            int kc = (s & 3) * 4;
            float4 v = *(const float4*)(X + (size_t)(row0 + r) * D + k0 + kc);
            As[kc + 0][r] = v.x; As[kc + 1][r] = v.y;
            As[kc + 2][r] = v.z; As[kc + 3][r] = v.w;
        }
        {
            int kr = tid >> 4;
            int c = (tid & 15) * 4;
            float4 v = *(const float4*)(B + (size_t)(k0 + kr) * D + col0 + c);
            *(float4*)&Bs[kr][c] = v;
        }
        __syncthreads();
#pragma unroll
        for (int p = 0; p < 16; p++) {
            float4 a0 = *(const float4*)&As[p][ty8];
            float4 a1 = *(const float4*)&As[p][ty8 + 4];
            float4 bv = *(const float4*)&Bs[p][tx4];
            ull ap[4], bd[4];
            ap[0] = pk2(a0.x, a0.y); ap[1] = pk2(a0.z, a0.w);
            ap[2] = pk2(a1.x, a1.y); ap[3] = pk2(a1.z, a1.w);
            bd[0] = pk2(bv.x, bv.x); bd[1] = pk2(bv.y, bv.y);
            bd[2] = pk2(bv.z, bv.z); bd[3] = pk2(bv.w, bv.w);
#pragma unroll
            for (int rp = 0; rp < 4; rp++)
#pragma unroll
                for (int c = 0; c < 4; c++) fma2(acc[rp][c], ap[rp], bd[c]);
        }
        __syncthreads();
    }
#pragma unroll
    for (int rp = 0; rp < 4; rp++) {
        float2 c0 = upk2(acc[rp][0]);
        float2 c1 = upk2(acc[rp][1]);
        float2 c2 = upk2(acc[rp][2]);
        float2 c3 = upk2(acc[rp][3]);
        size_t base0 = (size_t)(row0 + ty8 + 2 * rp) * D + col0 + tx4;
        size_t base1 = base0 + D;
        *(float4*)(C + base0) = make_float4(c0.x, c1.x, c2.x, c3.x);
        *(float4*)(C + base1) = make_float4(c0.y, c1.y, c2.y, c3.y);
    }
}

// ---------------- kernel 2: al/ar = wx @ W_{l,r}[k].T (warp per row) ------
__global__ __launch_bounds__(256) void k_alar(const float* __restrict__ Wl,
                                              const float* __restrict__ Wr) {
    const int idx = blockIdx.x * 8 + (threadIdx.x >> 5);  // 0 .. KK*N-1
    const int lane = threadIdx.x & 31;
    const int k = idx >> 12;          // N = 4096 = 2^12
    const int n = idx & (N - 1);

    const float* wxr = g_wx + (size_t)(k * N + n) * D;
    const float* wl = Wl + (size_t)k * 4 * D;
    const float* wr = Wr + (size_t)k * 4 * D;

    float s[8] = {0, 0, 0, 0, 0, 0, 0, 0};
#pragma unroll 2
    for (int c = lane; c < D; c += 32) {
        float v = wxr[c];
        s[0] = fmaf(v, wl[0 * D + c], s[0]);
        s[1] = fmaf(v, wl[1 * D + c], s[1]);
        s[2] = fmaf(v, wl[2 * D + c], s[2]);
        s[3] = fmaf(v, wl[3 * D + c], s[3]);
        s[4] = fmaf(v, wr[0 * D + c], s[4]);
        s[5] = fmaf(v, wr[1 * D + c], s[5]);
        s[6] = fmaf(v, wr[2 * D + c], s[6]);
        s[7] = fmaf(v, wr[3 * D + c], s[7]);
    }
#pragma unroll
    for (int r = 0; r < 8; r++)
#pragma unroll
        for (int o = 16; o; o >>= 1) s[r] += __shfl_xor_sync(0xffffffffu, s[r], o);

    if (lane == 0) {
        float* a = g_al + (size_t)(k * N + n) * 4;
        float* b = g_ar + (size_t)(k * N + n) * 4;
        a[0] = s[0]; a[1] = s[1]; a[2] = s[2]; a[3] = s[3];
        b[0] = s[4]; b[1] = s[5]; b[2] = s[6]; b[3] = s[7];
    }
}

// ---------------- kernel 3a: mask scan + deterministic compaction ----------
__global__ __launch_bounds__(256) void k_scan(const int* __restrict__ sup,
                                              const int* __restrict__ asup) {
    const int n = blockIdx.x;
    const int tid = threadIdx.x;
    const int lane = tid & 31;
    const int warp = tid >> 5;

    __shared__ int s_iwred[8];
    __shared__ int s_total;

    const int4* p0 = (const int4*)(asup + (size_t)0 * N * N + (size_t)n * N);
    const int4* p1 = (const int4*)(asup + (size_t)1 * N * N + (size_t)n * N);
    const int4* p2 = (const int4*)(asup + (size_t)2 * N * N + (size_t)n * N);
    const int4* q0 = (const int4*)(sup  + (size_t)0 * N * N + (size_t)n * N);
    const int4* q1 = (const int4*)(sup  + (size_t)1 * N * N + (size_t)n * N);
    const int4* q2 = (const int4*)(sup  + (size_t)2 * N * N + (size_t)n * N);

    int flags[16];
    int cnt = 0;
#pragma unroll
    for (int j = 0; j < 4; j++) {
        int idx = tid * 4 + j;
        int4 a0 = __ldg(&p0[idx]); int4 a1 = __ldg(&p1[idx]); int4 a2 = __ldg(&p2[idx]);
        int4 b0 = __ldg(&q0[idx]); int4 b1 = __ldg(&q1[idx]); int4 b2 = __ldg(&q2[idx]);
        int f;
        f = (a0.x != 0) | ((a1.x != 0) << 1) | ((a2.x != 0) << 2)
          | ((b0.x != 0) << 3) | ((b1.x != 0) << 4) | ((b2.x != 0) << 5);
        flags[j * 4 + 0] = f; cnt += (f != 0);
        f = (a0.y != 0) | ((a1.y != 0) << 1) | ((a2.y != 0) << 2)
          | ((b0.y != 0) << 3) | ((b1.y != 0) << 4) | ((b2.y != 0) << 5);
        flags[j * 4 + 1] = f; cnt += (f != 0);
        f = (a0.z != 0) | ((a1.z != 0) << 1) | ((a2.z != 0) << 2)
          | ((b0.z != 0) << 3) | ((b1.z != 0) << 4) | ((b2.z != 0) << 5);
        flags[j * 4 + 2] = f; cnt += (f != 0);
        f = (a0.w != 0) | ((a1.w != 0) << 1) | ((a2.w != 0) << 2)
          | ((b0.w != 0) << 3) | ((b1.w != 0) << 4) | ((b2.w != 0) << 5);
        flags[j * 4 + 3] = f; cnt += (f != 0);
    }

    // exclusive prefix over per-thread counts (order-preserving => deterministic)
    int inc = cnt;
#pragma unroll
    for (int o = 1; o < 32; o <<= 1) {
        int t = __shfl_up_sync(0xffffffffu, inc, o);
        if (lane >= o) inc += t;
    }
    if (lane == 31) s_iwred[warp] = inc;
    __syncthreads();
    if (tid < 8) {
        int v = s_iwred[tid];
#pragma unroll
        for (int o = 1; o < 8; o <<= 1) {
            int t = __shfl_up_sync(0xffu, v, o);
            if (tid >= o) v += t;
        }
        s_iwred[tid] = v;
        if (tid == 7) s_total = v;
    }
    __syncthreads();
    int off = (warp ? s_iwred[warp - 1] : 0) + inc - cnt;
    int* dst = g_packed + (size_t)n * MAXC;
#pragma unroll
    for (int c = 0; c < 16; c++) {
        int f = flags[c];
        if (f) {
            if (off < MAXC) dst[off] = (tid * 16 + c) | (f << 16);
            off++;
        }
    }
    if (tid == 0) g_cnt[n] = min(s_total, MAXC);
}

// ---------------- kernel 3b: scores + softmax + gather + ELU ---------------
__global__ __launch_bounds__(256) void k_gather(float* __restrict__ out) {
    const int n = blockIdx.x;
    const int tid = threadIdx.x;
    const int lane = tid & 31;
    const int warp = tid >> 5;

    __shared__ int   s_packed[MAXC];
    __shared__ float s_sc[KK][MAXC];
    __shared__ float s_red[8][256];
    __shared__ float s_al[12];
    __shared__ float s_wred[8];
    __shared__ float s_b;

    if (tid < 12) s_al[tid] = g_al[(size_t)((tid >> 2) * N + n) * 4 + (tid & 3)];
    const int cnt_all = g_cnt[n];

    const int* src = g_packed + (size_t)n * MAXC;
    for (int i = tid; i < cnt_all; i += 256) s_packed[i] = src[i];
    __syncthreads();

    // ---- phase B: scores for all 3 k ----
    for (int i = tid; i < cnt_all; i += 256) {
        int pk = s_packed[i];
        int m = pk & 0xFFFF;
        int f = pk >> 16;
#pragma unroll
        for (int k = 0; k < KK; k++) {
            float4 arv = *(const float4*)(g_ar + (size_t)(k * N + m) * 4);
            float sc = 0.f;
            if (f & 1) sc += s_al[k * 4 + 0] + arv.x;
            if (f & 2) sc += s_al[k * 4 + 1] + arv.y;
            if (f & 4) sc += s_al[k * 4 + 2] + arv.z;
            if (f & (8 << k)) sc += s_al[k * 4 + 3] + arv.w;
            bool act = (f & (7 | (8 << k))) != 0;
            s_sc[k][i] = (act && sc != 0.f) ? sc : -INFINITY;
        }
    }
    __syncthreads();

    // ---- phase C: per-k softmax + warp-distributed gather-accumulate ----
    float acc[8] = {0, 0, 0, 0, 0, 0, 0, 0};
#pragma unroll 1
    for (int k = 0; k < KK; k++) {
        float mx = -INFINITY;
        for (int i = tid; i < cnt_all; i += 256) mx = fmaxf(mx, s_sc[k][i]);
#pragma unroll
        for (int o = 16; o; o >>= 1) mx = fmaxf(mx, __shfl_xor_sync(0xffffffffu, mx, o));
        if (lane == 0) s_wred[warp] = mx;
        __syncthreads();
        if (tid < 8) {
            float v = s_wred[tid];
#pragma unroll
            for (int o = 4; o; o >>= 1) v = fmaxf(v, __shfl_xor_sync(0xffu, v, o));
            if (tid == 0) s_b = v;
        }
        __syncthreads();
        mx = s_b;
        __syncthreads();

        if (mx != -INFINITY) {     // uniform branch
            float sum = 0.f;
            for (int i = tid; i < cnt_all; i += 256) {
                float s = s_sc[k][i];
                float e = (s == -INFINITY) ? 0.f : expf(s - mx);
                s_sc[k][i] = e;
                sum += e;
            }
#pragma unroll
            for (int o = 16; o; o >>= 1) sum += __shfl_xor_sync(0xffffffffu, sum, o);
            if (lane == 0) s_wred[warp] = sum;
            __syncthreads();
            if (tid < 8) {
                float v = s_wred[tid];
#pragma unroll
                for (int o = 4; o; o >>= 1) v += __shfl_xor_sync(0xffu, v, o);
                if (tid == 0) s_b = v;
            }
            __syncthreads();
            const float inv = 1.f / s_b;
            const float* wxk = g_wx + (size_t)k * N * D;
#pragma unroll 2
            for (int i = warp; i < cnt_all; i += 8) {
                float p = s_sc[k][i];
                if (p > 0.f) {                     // warp-uniform (smem bcast)
                    int m = s_packed[i] & 0xFFFF;
                    const float4* rp = (const float4*)(wxk + (size_t)m * D) + (lane << 1);
                    float4 v0 = __ldg(rp);
                    float4 v1 = __ldg(rp + 1);
                    float w = p * inv;
                    acc[0] = fmaf(w, v0.x, acc[0]);
                    acc[1] = fmaf(w, v0.y, acc[1]);
                    acc[2] = fmaf(w, v0.z, acc[2]);
                    acc[3] = fmaf(w, v0.w, acc[3]);
                    acc[4] = fmaf(w, v1.x, acc[4]);
                    acc[5] = fmaf(w, v1.y, acc[5]);
                    acc[6] = fmaf(w, v1.z, acc[6]);
                    acc[7] = fmaf(w, v1.w, acc[7]);
                }
            }
        }
        __syncthreads();
    }

    *(float4*)&s_red[warp][lane * 8]     = make_float4(acc[0], acc[1], acc[2], acc[3]);
    *(float4*)&s_red[warp][lane * 8 + 4] = make_float4(acc[4], acc[5], acc[6], acc[7]);
    __syncthreads();
    float a = 0.f;
#pragma unroll
    for (int w = 0; w < 8; w++) a += s_red[w][tid];
    float r = a > 0.f ? a : expm1f(a);
    out[(size_t)n * D + tid] = r;
}

// ---------------- launcher -------------------------------------------------
extern "C" void kernel_launch(void* const* d_in, const int* in_sizes, int n_in,
                              void* d_out, int out_size) {
    const float* x    = (const float*)d_in[0];
    const int*   sup  = (const int*)d_in[1];   // supports [K,N,N]
    const int*   asup = (const int*)d_in[2];   // atten_supports [R,N,N]
    const float* Wt   = (const float*)d_in[3]; // [K,DIN,DOUT]
    const float* Wl   = (const float*)d_in[4]; // [K,R+1,DOUT]
    const float* Wr   = (const float*)d_in[5]; // [K,R+1,DOUT]
    float* out = (float*)d_out;

    k_scan<<<N, 256>>>(sup, asup);
    dim3 g1(N / 128, D / 64, KK);
    k_gemm<<<g1, 256>>>(x, Wt);
    k_alar<<<(KK * N) / 8, 256>>>(Wl, Wr);
    k_gather<<<N, 256>>>(out);
    (void)in_sizes; (void)n_in; (void)out_size;
}